// round 17
// baseline (speedup 1.0000x reference)
#include <cuda_runtime.h>
#include <cuda_fp16.h>
#include <cstdint>

#define BB 2
#define HH 16
#define SS 2048
#define DD 64
#define NTHREADS 256
#define CTX_ELEMS (BB*HH*SS*DD)
#define NHEADS 32
#define NT64 32                // key tiles of 64
#define QTILE_BYTES 32768      // Q frag image per 128-row block (hi+lo)
#define KTILE 8192             // K frag image per 64-key tile (hi only)
#define VTILE 8192             // V frag image per 64-key tile (hi only)
#define SMEM_DYN 32768         // pass B: K pp [0,16K) + V pp [16K,32K)
#define EXPC 0.18033688011112042f   // 0.125 * log2(e)
#define MASK_WORDS (BB*SS*64)

__device__ __align__(16) unsigned char g_qf[(size_t)NHEADS*16*QTILE_BYTES];
__device__ __align__(16) unsigned char g_kf[(size_t)NHEADS*NT64*KTILE];
__device__ __align__(16) unsigned char g_vf[(size_t)NHEADS*NT64*VTILE];
__device__ __align__(16) unsigned int  g_maskbits[MASK_WORDS];

__device__ __forceinline__ uint32_t pack2hi(float a, float b) {
    __half ha = __float2half_rn(a), hb = __float2half_rn(b);
    return (uint32_t)__half_as_ushort(ha) | ((uint32_t)__half_as_ushort(hb) << 16);
}
__device__ __forceinline__ uint32_t pack2lo(float a, float b) {
    __half ha = __float2half_rn(a), hb = __float2half_rn(b);
    __half la = __float2half_rn(a - __half2float(ha));
    __half lb = __float2half_rn(b - __half2float(hb));
    return (uint32_t)__half_as_ushort(la) | ((uint32_t)__half_as_ushort(lb) << 16);
}

// ---- prepass: Q(512) K(1024) V(1024) mask(1024) blocks ----
__global__ void prepass_kernel(const float* __restrict__ Q,
                               const float* __restrict__ K,
                               const float* __restrict__ V,
                               const int* __restrict__ M)
{
    const int bx = blockIdx.x;
    if (bx >= 2560) {
        const int w = (bx - 2560) * NTHREADS + threadIdx.x;
        const int* src = M + (size_t)w * 32;
        unsigned int bits = 0;
        #pragma unroll
        for (int j = 0; j < 32; j++) bits |= (src[j] != 0 ? 1u : 0u) << j;
        g_maskbits[w] = bits;
        return;
    }
    if (bx < 512) {
        // Q frag image: hi+lo (Q keeps full split precision)
        const int chunk = bx, head = chunk >> 4, sub = chunk & 15;
        const float* S_ = Q + (size_t)head * SS * DD;
        uint32_t* dst = (uint32_t*)(g_qf + (size_t)chunk * QTILE_BYTES);
        for (int i = threadIdx.x; i < 8192; i += NTHREADS) {
            int word = i & 7, lane = (i >> 3) & 31, kt = (i >> 8) & 3, mt = i >> 10;
            int ai = word & 3; bool lo = word >= 4;
            int r = (lane >> 2) + ((ai & 1) ? 8 : 0);
            int c = (lane & 3) * 2 + ((ai >= 2) ? 8 : 0);
            int row = sub * 128 + mt * 16 + r, col = kt * 16 + c;
            float f0 = S_[(size_t)row * DD + col], f1 = S_[(size_t)row * DD + col + 1];
            dst[i] = lo ? pack2lo(f0, f1) : pack2hi(f0, f1);
        }
        return;
    }
    if (bx < 1536) {
        // K frag image: hi ONLY (k_lo dead after QK 2-term change)
        const int chunk = bx - 512, head = chunk >> 5, sub = chunk & 31;
        const float* S_ = K + (size_t)head * SS * DD;
        uint32_t* dst = (uint32_t*)(g_kf + (size_t)chunk * KTILE);
        for (int i = threadIdx.x; i < 2048; i += NTHREADS) {
            int word = i & 1, lane = (i >> 1) & 31, kt = (i >> 6) & 3, j = (i >> 8) & 7;
            int key = sub * 64 + j * 8 + (lane >> 2);
            int dim = kt * 16 + (lane & 3) * 2 + (word ? 8 : 0);
            float f0 = S_[(size_t)key * DD + dim], f1 = S_[(size_t)key * DD + dim + 1];
            dst[i] = pack2hi(f0, f1);
        }
        return;
    }
    {
        // V frag image: hi only
        const int chunk = bx - 1536, head = chunk >> 5, sub = chunk & 31;
        const float* S_ = V + (size_t)head * SS * DD;
        uint32_t* dst = (uint32_t*)(g_vf + (size_t)chunk * VTILE);
        for (int i = threadIdx.x; i < 2048; i += NTHREADS) {
            int word = i & 1, lane = (i >> 1) & 31, u = (i >> 6) & 3, nt = (i >> 8) & 7;
            int key = sub * 64 + u * 16 + (lane & 3) * 2 + (word ? 8 : 0);
            int dim = nt * 8 + (lane >> 2);
            float f0 = S_[(size_t)key * DD + dim], f1 = S_[(size_t)(key + 1) * DD + dim];
            dst[i] = pack2hi(f0, f1);
        }
    }
}

// ---- main ----
__device__ __forceinline__ uint32_t smem_u32(const void* p) {
    uint32_t a;
    asm("{ .reg .u64 t; cvta.to.shared.u64 t, %1; cvt.u32.u64 %0, t; }" : "=r"(a) : "l"(p));
    return a;
}
__device__ __forceinline__ void cp16(uint32_t s, const void* g) {
    asm volatile("cp.async.cg.shared.global [%0], [%1], 16;" :: "r"(s), "l"(g));
}
__device__ __forceinline__ void mma_f16(float d[4], const uint32_t a[4],
                                        uint32_t b0, uint32_t b1) {
    asm volatile("mma.sync.aligned.m16n8k16.row.col.f32.f16.f16.f32 "
        "{%0,%1,%2,%3}, {%4,%5,%6,%7}, {%8,%9}, {%0,%1,%2,%3};"
        : "+f"(d[0]), "+f"(d[1]), "+f"(d[2]), "+f"(d[3])
        : "r"(a[0]), "r"(a[1]), "r"(a[2]), "r"(a[3]), "r"(b0), "r"(b1));
}

__global__ __launch_bounds__(NTHREADS, 2)
void attn_main(float* __restrict__ out)
{
    extern __shared__ unsigned char smem[];
    __shared__ float sSum[128];
    const uint32_t sb = smem_u32(smem);
    const int tid = threadIdx.x, w = tid >> 5, lane = tid & 31;
    const int head = blockIdx.x >> 4, qblk = blockIdx.x & 15;
    const int b = head >> 4;
    const int q0 = qblk * 128;
    const int r0 = 16 * w + (lane >> 2);
    const int cq = (lane & 3) * 2;

    // Q fragments resident (fp16 hi/lo)
    uint32_t qh[4][4], ql[4][4];
    {
        const unsigned char* qc = g_qf + (size_t)(head * 16 + qblk) * QTILE_BYTES;
        #pragma unroll
        for (int kt = 0; kt < 4; kt++) {
            const unsigned char* p = qc + (size_t)(((w * 4 + kt) * 32 + lane) * 32);
            uint4 h = *(const uint4*)p, l = *(const uint4*)(p + 16);
            qh[kt][0] = h.x; qh[kt][1] = h.y; qh[kt][2] = h.z; qh[kt][3] = h.w;
            ql[kt][0] = l.x; ql[kt][1] = l.y; ql[kt][2] = l.z; ql[kt][3] = l.w;
        }
    }
    const unsigned char* mrow0 = (const unsigned char*)g_maskbits + (size_t)(b * SS + q0 + r0) * 256;
    const unsigned char* mrow1 = mrow0 + 8 * 256;
    const unsigned char* kbase = g_kf + (size_t)head * NT64 * KTILE;
    const unsigned char* vbase = g_vf + (size_t)head * NT64 * VTILE;

    // ================= pass A: rowsums (1-term fp16, K-hi) =================
    {
        #pragma unroll
        for (int i = 0; i < 2; i++) cp16(sb + tid * 16 + i * 4096, kbase + tid * 16 + i * 4096);
        asm volatile("cp.async.commit_group;");
    }
    float rs0 = 0.f, rs1 = 0.f;
    for (int t = 0; t < NT64; t++) {
        if (t < NT64 - 1) {
            const unsigned char* src = kbase + (size_t)(t + 1) * KTILE;
            uint32_t d0 = sb + ((t + 1) & 1) * 8192;
            #pragma unroll
            for (int i = 0; i < 2; i++) cp16(d0 + tid * 16 + i * 4096, src + tid * 16 + i * 4096);
            asm volatile("cp.async.commit_group;");
            asm volatile("cp.async.wait_group 1;");
        } else {
            asm volatile("cp.async.wait_group 0;");
        }
        __syncthreads();
        const unsigned char* Kb = smem + (t & 1) * 8192;
        uint2 mA = *(const uint2*)(mrow0 + t * 8);
        uint2 mB = *(const uint2*)(mrow1 + t * 8);
        #pragma unroll
        for (int j = 0; j < 8; j++) {
            float d[4] = {0.f, 0.f, 0.f, 0.f};
            #pragma unroll
            for (int kt = 0; kt < 4; kt++) {
                uint2 bh = *(const uint2*)(Kb + ((j * 4 + kt) * 32 + lane) * 8);
                mma_f16(d, qh[kt], bh.x, bh.y);
            }
            const int sh = 8 * (j & 3) + cq;
            const uint32_t ma = ((j < 4) ? mA.x : mA.y) >> sh;
            const uint32_t mb2 = ((j < 4) ? mB.x : mB.y) >> sh;
            rs0 += ((ma  & 1) ? 0.f : exp2f(d[0] * EXPC)) + ((ma  & 2) ? 0.f : exp2f(d[1] * EXPC));
            rs1 += ((mb2 & 1) ? 0.f : exp2f(d[2] * EXPC)) + ((mb2 & 2) ? 0.f : exp2f(d[3] * EXPC));
        }
        __syncthreads();
    }
    rs0 += __shfl_xor_sync(0xFFFFFFFFu, rs0, 1); rs0 += __shfl_xor_sync(0xFFFFFFFFu, rs0, 2);
    rs1 += __shfl_xor_sync(0xFFFFFFFFu, rs1, 1); rs1 += __shfl_xor_sync(0xFFFFFFFFu, rs1, 2);
    if ((lane & 3) == 0) { sSum[r0] = rs0; sSum[r0 + 8] = rs1; }
    __syncthreads();
    const float inv0 = 1.0f / sSum[r0];
    const float inv1 = 1.0f / sSum[r0 + 8];

    // ================= pass B: QK 2-term + att + PV 1-term =================
    float dacc[8][4];
    #pragma unroll
    for (int nt = 0; nt < 8; nt++) { dacc[nt][0]=0.f; dacc[nt][1]=0.f; dacc[nt][2]=0.f; dacc[nt][3]=0.f; }
    {
        #pragma unroll
        for (int i = 0; i < 2; i++) cp16(sb + tid * 16 + i * 4096, kbase + tid * 16 + i * 4096);
        #pragma unroll
        for (int i = 0; i < 2; i++) cp16(sb + 16384 + tid * 16 + i * 4096, vbase + tid * 16 + i * 4096);
        asm volatile("cp.async.commit_group;");
    }
    float* att = out + (size_t)CTX_ELEMS + (size_t)head * SS * SS;
    for (int t = 0; t < NT64; t++) {
        if (t < NT64 - 1) {
            const unsigned char* sk = kbase + (size_t)(t + 1) * KTILE;
            const unsigned char* sv = vbase + (size_t)(t + 1) * VTILE;
            uint32_t dk = sb + ((t + 1) & 1) * 8192;
            uint32_t dv = sb + 16384 + ((t + 1) & 1) * 8192;
            #pragma unroll
            for (int i = 0; i < 2; i++) cp16(dk + tid * 16 + i * 4096, sk + tid * 16 + i * 4096);
            #pragma unroll
            for (int i = 0; i < 2; i++) cp16(dv + tid * 16 + i * 4096, sv + tid * 16 + i * 4096);
            asm volatile("cp.async.commit_group;");
            asm volatile("cp.async.wait_group 1;");
        } else {
            asm volatile("cp.async.wait_group 0;");
        }
        __syncthreads();
        const unsigned char* Kb = smem + (t & 1) * 8192;
        const unsigned char* Vb = smem + 16384 + (t & 1) * 8192;
        uint2 mA = *(const uint2*)(mrow0 + t * 8);
        uint2 mB = *(const uint2*)(mrow1 + t * 8);
        #pragma unroll
        for (int u = 0; u < 4; u++) {
            const int j0 = 2 * u, j1 = 2 * u + 1;
            float d0[4] = {0.f,0.f,0.f,0.f}, d1[4] = {0.f,0.f,0.f,0.f};
            #pragma unroll
            for (int kt = 0; kt < 4; kt++) {
                uint2 bh0 = *(const uint2*)(Kb + ((j0 * 4 + kt) * 32 + lane) * 8);
                mma_f16(d0, qh[kt], bh0.x, bh0.y);
                mma_f16(d0, ql[kt], bh0.x, bh0.y);
                uint2 bh1 = *(const uint2*)(Kb + ((j1 * 4 + kt) * 32 + lane) * 8);
                mma_f16(d1, qh[kt], bh1.x, bh1.y);
                mma_f16(d1, ql[kt], bh1.x, bh1.y);
            }
            const int sh0 = 8 * (j0 & 3) + cq, sh1 = 8 * (j1 & 3) + cq;
            const uint32_t ma0 = ((j0 < 4) ? mA.x : mA.y) >> sh0;
            const uint32_t mb0 = ((j0 < 4) ? mB.x : mB.y) >> sh0;
            const uint32_t ma1 = ((j1 < 4) ? mA.x : mA.y) >> sh1;
            const uint32_t mb1 = ((j1 < 4) ? mB.x : mB.y) >> sh1;
            float p0 = (ma0 & 1) ? 0.f : exp2f(d0[0] * EXPC) * inv0;
            float p1 = (ma0 & 2) ? 0.f : exp2f(d0[1] * EXPC) * inv0;
            float p2 = (mb0 & 1) ? 0.f : exp2f(d0[2] * EXPC) * inv1;
            float p3 = (mb0 & 2) ? 0.f : exp2f(d0[3] * EXPC) * inv1;
            float p4 = (ma1 & 1) ? 0.f : exp2f(d1[0] * EXPC) * inv0;
            float p5 = (ma1 & 2) ? 0.f : exp2f(d1[1] * EXPC) * inv0;
            float p6 = (mb1 & 1) ? 0.f : exp2f(d1[2] * EXPC) * inv1;
            float p7 = (mb1 & 2) ? 0.f : exp2f(d1[3] * EXPC) * inv1;
            // attention output
            float* a0 = att + (size_t)(q0 + r0) * SS + t * 64 + 16 * u + cq;
            *(float2*)a0 = make_float2(p0, p1);
            *(float2*)(a0 + 8 * (size_t)SS) = make_float2(p2, p3);
            *(float2*)(a0 + 8) = make_float2(p4, p5);
            *(float2*)(a0 + 8 * (size_t)SS + 8) = make_float2(p6, p7);
            // E fragment (A layout), fp16 hi only
            uint32_t eh[4];
            eh[0] = pack2hi(p0, p1); eh[1] = pack2hi(p2, p3);
            eh[2] = pack2hi(p4, p5); eh[3] = pack2hi(p6, p7);
            // PV 1-term: eh x vh
            #pragma unroll
            for (int nt = 0; nt < 8; nt++) {
                uint2 vb = *(const uint2*)(Vb + ((nt * 4 + u) * 32 + lane) * 8);
                mma_f16(dacc[nt], eh, vb.x, vb.y);
            }
        }
        __syncthreads();
    }

    // context epilogue (probs already normalized)
    float* ctx = out + (size_t)head * SS * DD;
    #pragma unroll
    for (int nt = 0; nt < 8; nt++) {
        const int col = 8 * nt + cq;
        *(float2*)(ctx + (size_t)(q0 + r0) * DD + col)     = make_float2(dacc[nt][0], dacc[nt][1]);
        *(float2*)(ctx + (size_t)(q0 + r0 + 8) * DD + col) = make_float2(dacc[nt][2], dacc[nt][3]);
    }
}

extern "C" void kernel_launch(void* const* d_in, const int* in_sizes, int n_in,
                              void* d_out, int out_size)
{
    (void)in_sizes; (void)n_in; (void)out_size;
    const float* Q = (const float*)d_in[0];
    const float* K = (const float*)d_in[1];
    const float* V = (const float*)d_in[2];
    const int*   M = (const int*)d_in[3];
    float* out = (float*)d_out;

    cudaFuncSetAttribute(attn_main,
                         cudaFuncAttributeMaxDynamicSharedMemorySize, SMEM_DYN);

    prepass_kernel<<<3584, NTHREADS>>>(Q, K, V, M);
    attn_main<<<NHEADS * 16, NTHREADS, SMEM_DYN>>>(out);
}